// round 10
// baseline (speedup 1.0000x reference)
#include <cuda_runtime.h>

// Problem dims (fixed by the reference setup_inputs)
#define B_    256
#define F_    300
#define JC_   1600
#define NC_   60
#define J4_   (JC_ / 4)    // 400 float4 per frame
#define CHUNK 30           // frames per pooling tile
#define NCH   (F_ / CHUNK) // 10 chunks
#define NTILE (B_ * NCH)   // 2560 pooling tiles
#define NQ    (NC_ / 4)    // 15 n-quads
#define BTILE 16           // batch rows per fc task
#define BT_N  (B_ / BTILE) // 16 batch tiles
#define NFCT  (NQ * BT_N)  // 240 fc tasks
#define THREADS 400

// Pooled (un-normalized) feature sums [B, JC] — 1.6 MB, built via red.global
__device__ float g_pooled[(size_t)B_ * JC_];

// Grid-barrier state. g_gen increments monotonically across graph replays
// (equality-compared, wrap is harmless); g_cnt is reset by the last arriver.
__device__ unsigned g_cnt = 0;
__device__ volatile unsigned g_gen = 0;

__device__ __forceinline__ void grid_barrier() {
    __syncthreads();
    if (threadIdx.x == 0) {
        __threadfence();                       // publish phase-1 writes
        const unsigned gen = g_gen;
        if (atomicAdd(&g_cnt, 1) == gridDim.x - 1) {
            g_cnt = 0;
            __threadfence();
            g_gen = gen + 1;                   // release
        } else {
            while (g_gen == gen) __nanosleep(64);
        }
        __threadfence();                       // acquire
    }
    __syncthreads();
}

// ---------------------------------------------------------------------------
// Fused persistent kernel. grid = 2 x #SMs (all blocks resident), block = 400.
// Phase 1: round-robin over 2560 (b, chunk) tiles; thread j4 sums its float4
//          column over the tile's valid frames, red.global into g_pooled.
// Barrier: software grid sync (all blocks resident by __launch_bounds__(400,2)).
// Phase 2: blocks < 240 run one (quad q, 16-row batch tile) FC task:
//          W[:,4q..4q+3] slice -> smem; 8 warps x 2 rows, coalesced L2 reads
//          of g_pooled (hot), LDS.128 of sW, 8 FMA chains; mean folded into
//          the epilogue; len<=1 -> x frame 0 with inv=1.
// ---------------------------------------------------------------------------
__global__ __launch_bounds__(THREADS, 2) void fused_kernel(
    const float* __restrict__ x,       // [B, F, JC]
    const int*   __restrict__ lengths, // [B]
    const float* __restrict__ W,       // [JC, NC] row-major
    const float* __restrict__ bias,    // [NC]
    float*       __restrict__ out)     // [B, NC]
{
    __shared__ float4 sW[JC_];         // 25.6 KB (phase 2)

    const int tid = threadIdx.x;
    const int bid = blockIdx.x;

    // ================= Phase 1: pooling =================
    for (int tile = bid; tile < NTILE; tile += gridDim.x) {
        const int b = tile / NCH;
        const int c = tile - b * NCH;
        const int len = lengths[b];
        const int f0 = c * CHUNK;
        if (f0 >= len) continue;
        const int f1 = min(f0 + CHUNK, len);

        const float4* __restrict__ xb =
            reinterpret_cast<const float4*>(x + (size_t)b * F_ * JC_);
        const int j4 = tid;            // 0..399

        float ax = 0.f, ay = 0.f, az = 0.f, aw = 0.f;
        int f = f0;
        for (; f + 4 <= f1; f += 4) {
            float4 v0 = __ldcs(&xb[(size_t)(f + 0) * J4_ + j4]);
            float4 v1 = __ldcs(&xb[(size_t)(f + 1) * J4_ + j4]);
            float4 v2 = __ldcs(&xb[(size_t)(f + 2) * J4_ + j4]);
            float4 v3 = __ldcs(&xb[(size_t)(f + 3) * J4_ + j4]);
            ax += v0.x + v1.x + v2.x + v3.x;
            ay += v0.y + v1.y + v2.y + v3.y;
            az += v0.z + v1.z + v2.z + v3.z;
            aw += v0.w + v1.w + v2.w + v3.w;
        }
        for (; f < f1; f++) {
            float4 v = __ldcs(&xb[(size_t)f * J4_ + j4]);
            ax += v.x; ay += v.y; az += v.z; aw += v.w;
        }
        float* dst = g_pooled + (size_t)b * JC_ + j4 * 4;
        asm volatile("red.global.add.v4.f32 [%0], {%1, %2, %3, %4};"
                     :: "l"(dst), "f"(ax), "f"(ay), "f"(az), "f"(aw)
                     : "memory");
    }

    // ================= Grid barrier =================
    grid_barrier();

    // ================= Phase 2: FC =================
    if (bid < NFCT) {
        const int q  = bid % NQ;               // 0..14
        const int b0 = (bid / NQ) * BTILE;     // batch tile base

        // W slice -> smem (all 400 threads)
        const float4* __restrict__ W4 = reinterpret_cast<const float4*>(W);
        for (int j = tid; j < JC_; j += THREADS)
            sW[j] = W4[(size_t)j * NQ + q];
        __syncthreads();

        if (tid < 256) {
            const int w = tid >> 5;            // 0..7
            const int l = tid & 31;
            const int bA = b0 + w;
            const int bB = b0 + w + 8;
            const int lenA = lengths[bA];
            const int lenB = lengths[bB];
            const float* __restrict__ srcA = (lenA <= 1)
                ? (x + (size_t)bA * F_ * JC_) : (g_pooled + (size_t)bA * JC_);
            const float* __restrict__ srcB = (lenB <= 1)
                ? (x + (size_t)bB * F_ * JC_) : (g_pooled + (size_t)bB * JC_);
            const float invA = (lenA <= 1) ? 1.0f : 1.0f / (float)lenA;
            const float invB = (lenB <= 1) ? 1.0f : 1.0f / (float)lenB;

            float4 a0 = make_float4(0.f, 0.f, 0.f, 0.f);
            float4 a1 = a0;
#pragma unroll 5
            for (int k = 0; k < JC_ / 32; k++) {   // 50 iterations
                const int j = k * 32 + l;
                const float pA = srcA[j];          // coalesced, L2-hot
                const float pB = srcB[j];
                const float4 wv = sW[j];           // conflict-free LDS.128
                a0.x += pA * wv.x; a0.y += pA * wv.y;
                a0.z += pA * wv.z; a0.w += pA * wv.w;
                a1.x += pB * wv.x; a1.y += pB * wv.y;
                a1.z += pB * wv.z; a1.w += pB * wv.w;
            }
#pragma unroll
            for (int off = 16; off > 0; off >>= 1) {
                a0.x += __shfl_xor_sync(0xFFFFFFFF, a0.x, off);
                a0.y += __shfl_xor_sync(0xFFFFFFFF, a0.y, off);
                a0.z += __shfl_xor_sync(0xFFFFFFFF, a0.z, off);
                a0.w += __shfl_xor_sync(0xFFFFFFFF, a0.w, off);
                a1.x += __shfl_xor_sync(0xFFFFFFFF, a1.x, off);
                a1.y += __shfl_xor_sync(0xFFFFFFFF, a1.y, off);
                a1.z += __shfl_xor_sync(0xFFFFFFFF, a1.z, off);
                a1.w += __shfl_xor_sync(0xFFFFFFFF, a1.w, off);
            }
            if (l == 0) {
                const int n = 4 * q;
                const float c0 = bias[n + 0], c1 = bias[n + 1];
                const float c2 = bias[n + 2], c3 = bias[n + 3];
                float* oA = out + (size_t)bA * NC_ + n;
                oA[0] = a0.x * invA + c0; oA[1] = a0.y * invA + c1;
                oA[2] = a0.z * invA + c2; oA[3] = a0.w * invA + c3;
                float* oB = out + (size_t)bB * NC_ + n;
                oB[0] = a1.x * invB + c0; oB[1] = a1.y * invB + c1;
                oB[2] = a1.z * invB + c2; oB[3] = a1.w * invB + c3;
            }
        }
    }
}

extern "C" void kernel_launch(void* const* d_in, const int* in_sizes, int n_in,
                              void* d_out, int out_size)
{
    const float* x       = (const float*)d_in[0];
    const int*   lengths = (const int*)  d_in[1];
    const float* W       = (const float*)d_in[2];
    const float* bias    = (const float*)d_in[3];
    float*       out     = (float*)d_out;

    // zero the accumulator (graph-capturable memset node; no allocation)
    void* pooled_ptr = nullptr;
    cudaGetSymbolAddress(&pooled_ptr, g_pooled);
    cudaMemsetAsync(pooled_ptr, 0, sizeof(float) * (size_t)B_ * JC_);

    // 2 blocks per SM, all resident (required by the software grid barrier)
    int dev = 0, sms = 148;
    cudaGetDevice(&dev);
    cudaDeviceGetAttribute(&sms, cudaDevAttrMultiProcessorCount, dev);
    const int grid = 2 * sms;

    fused_kernel<<<grid, THREADS>>>(x, lengths, W, bias, out);
}

// round 11
// speedup vs baseline: 1.0057x; 1.0057x over previous
#include <cuda_runtime.h>

// Problem dims (fixed by the reference setup_inputs)
#define B_    256
#define F_    300
#define JC_   1600
#define NC_   60
#define J4_   (JC_ / 4)    // 400 float4 per frame
#define CHUNK 30           // frames per pooling tile
#define NCH   (F_ / CHUNK) // 10 chunks
#define NGRP  6            // j-groups in inline FC
#define THREADS 400

// Pooled (un-normalized) feature sums [B, JC] — 1.6 MB, built via red.global
__device__ float    g_pooled[(size_t)B_ * JC_];
// Per-batch chunk-completion counters (memset to 0 each launch)
__device__ unsigned g_done[B_];

// ---------------------------------------------------------------------------
// Fused kernel: chunk pooling + dynamic last-block FC per batch row.
// grid = (B, NCH), block = 400 (proven high-MLP pool shape, 4 blocks/SM).
//  - Pool: thread j4 sums its float4 column over the chunk's valid frames,
//    red.global.add.v4 into g_pooled[b].
//  - All 10 chunk blocks of batch b arrive on g_done[b] (fence before add).
//    The LAST arriver computes out[b,:] inline: pooled row -> smem (ldcg),
//    6 groups x 60 coalesced-n outputs, unroll 8, smem combine + bias.
//    This overlaps FC latency with other blocks' DRAM streaming.
// ---------------------------------------------------------------------------
__global__ __launch_bounds__(THREADS, 4) void fused_kernel(
    const float* __restrict__ x,       // [B, F, JC]
    const int*   __restrict__ lengths, // [B]
    const float* __restrict__ W,       // [JC, NC] row-major
    const float* __restrict__ bias,    // [NC]
    float*       __restrict__ out)     // [B, NC]
{
    __shared__ float sp[JC_];          // 6.4 KB pooled row (FC path)
    __shared__ float red_s[NGRP][NC_]; // 1.44 KB group partials
    __shared__ int   s_last;           // "this block does FC" flag

    const int b   = blockIdx.x;
    const int c   = blockIdx.y;
    const int tid = threadIdx.x;
    const int len = lengths[b];

    // ---------------- pooling for this chunk ----------------
    const int f0 = c * CHUNK;
    if (f0 < len) {
        const int f1 = min(f0 + CHUNK, len);
        const float4* __restrict__ xb =
            reinterpret_cast<const float4*>(x + (size_t)b * F_ * JC_);
        const int j4 = tid;

        float ax = 0.f, ay = 0.f, az = 0.f, aw = 0.f;
        int f = f0;
        for (; f + 4 <= f1; f += 4) {
            float4 v0 = __ldcs(&xb[(size_t)(f + 0) * J4_ + j4]);
            float4 v1 = __ldcs(&xb[(size_t)(f + 1) * J4_ + j4]);
            float4 v2 = __ldcs(&xb[(size_t)(f + 2) * J4_ + j4]);
            float4 v3 = __ldcs(&xb[(size_t)(f + 3) * J4_ + j4]);
            ax += v0.x + v1.x + v2.x + v3.x;
            ay += v0.y + v1.y + v2.y + v3.y;
            az += v0.z + v1.z + v2.z + v3.z;
            aw += v0.w + v1.w + v2.w + v3.w;
        }
        for (; f < f1; f++) {
            float4 v = __ldcs(&xb[(size_t)f * J4_ + j4]);
            ax += v.x; ay += v.y; az += v.z; aw += v.w;
        }
        float* dst = g_pooled + (size_t)b * JC_ + j4 * 4;
        asm volatile("red.global.add.v4.f32 [%0], {%1, %2, %3, %4};"
                     :: "l"(dst), "f"(ax), "f"(ay), "f"(az), "f"(aw)
                     : "memory");
    }

    // ---------------- arrival; last block runs FC ----------------
    __syncthreads();                       // all reds of this block issued
    if (tid == 0) {
        __threadfence();                   // publish reds before counting
        const unsigned prev = atomicAdd(&g_done[b], 1u);
        s_last = (prev == NCH - 1) ? 1 : 0;
    }
    __syncthreads();
    if (!s_last) return;
    __threadfence();                       // acquire: see all batches' reds

    // ---- stage the (un-normalized) pooled row, or frame 0 if len<=1 ----
    const float inv = (len <= 1) ? 1.0f : 1.0f / (float)len;
    {
        const float4* __restrict__ src = (len <= 1)
            ? reinterpret_cast<const float4*>(x + (size_t)b * F_ * JC_)
            : reinterpret_cast<const float4*>(g_pooled + (size_t)b * JC_);
        float4 v = __ldcg(&src[tid]);      // .cg: bypass L1 (freshly red-written)
        reinterpret_cast<float4*>(sp)[tid] = v;
    }
    __syncthreads();

    // ---- FC: 6 groups x 60 outputs (n consecutive -> coalesced W) ----
    if (tid < NGRP * NC_) {
        const int g = tid / NC_;           // 0..5
        const int n = tid - g * NC_;       // 0..59
        const float* __restrict__ Wn = W + n;
        float acc = 0.f;
#pragma unroll 8
        for (int j = g; j < JC_; j += NGRP) {
            acc += sp[j] * Wn[(size_t)j * NC_];
        }
        red_s[g][n] = acc;
    }
    __syncthreads();

    if (tid < NC_) {
        float acc = bias[tid];
#pragma unroll
        for (int g = 0; g < NGRP; g++) acc += red_s[g][tid];
        out[(size_t)b * NC_ + tid] = acc * 1.0f
            + 0.0f;                        // (kept simple; mean applied below)
        // NOTE: mean must scale only the pooled dot, not the bias:
        //   out = (sum_j pooled_sum[j]*W[j,n]) * inv + bias[n]
        out[(size_t)b * NC_ + tid] = (acc - bias[tid]) * inv + bias[tid];
    }
}

extern "C" void kernel_launch(void* const* d_in, const int* in_sizes, int n_in,
                              void* d_out, int out_size)
{
    const float* x       = (const float*)d_in[0];
    const int*   lengths = (const int*)  d_in[1];
    const float* W       = (const float*)d_in[2];
    const float* bias    = (const float*)d_in[3];
    float*       out     = (float*)d_out;

    // zero accumulator + counters (graph-capturable memset nodes)
    void* pooled_ptr = nullptr;
    cudaGetSymbolAddress(&pooled_ptr, g_pooled);
    cudaMemsetAsync(pooled_ptr, 0, sizeof(float) * (size_t)B_ * JC_);
    void* done_ptr = nullptr;
    cudaGetSymbolAddress(&done_ptr, g_done);
    cudaMemsetAsync(done_ptr, 0, sizeof(unsigned) * B_);

    dim3 grid(B_, NCH);
    fused_kernel<<<grid, THREADS>>>(x, lengths, W, bias, out);
}

// round 12
// speedup vs baseline: 1.2468x; 1.2397x over previous
#include <cuda_runtime.h>

// Problem dims (fixed by the reference setup_inputs)
#define B_    256
#define F_    300
#define JC_   1600
#define NC_   60
#define J4_   (JC_ / 4)    // 400 float4 per frame
#define CHUNK 30           // frames per pooling tile
#define NCH   (F_ / CHUNK) // 10 chunks
#define NQ    (NC_ / 4)    // 15 n-quads
#define BTILE 16           // batch rows per fc block
#define BT_N  (B_ / BTILE) // 16 batch tiles

// Pooled (un-normalized) feature sums [B, JC] — 1.6 MB, built via red.global
__device__ float g_pooled[(size_t)B_ * JC_];

// ---------------------------------------------------------------------------
// Kernel 1: chunk pooling. grid = (B, NCH), block = 400.
// __launch_bounds__(400, 3): 53-reg budget -> unroll-8 loads batched in
// flight (the 40-reg cap at occupancy 4 was serializing them).
// ---------------------------------------------------------------------------
__global__ __launch_bounds__(400, 3) void pool_part_kernel(
    const float* __restrict__ x,       // [B, F, JC]
    const int*   __restrict__ lengths) // [B]
{
    const int b  = blockIdx.x;
    const int c  = blockIdx.y;
    const int j4 = threadIdx.x;

    const int len = lengths[b];
    const int f0  = c * CHUNK;
    if (f0 >= len) return;
    const int f1  = min(f0 + CHUNK, len);

    const float4* __restrict__ xb =
        reinterpret_cast<const float4*>(x + (size_t)b * F_ * JC_);

    float ax = 0.f, ay = 0.f, az = 0.f, aw = 0.f;
    int f = f0;
    // unroll by 8: up to 8 independent LDG.128 in flight per thread
    for (; f + 8 <= f1; f += 8) {
        float4 v0 = __ldcs(&xb[(size_t)(f + 0) * J4_ + j4]);
        float4 v1 = __ldcs(&xb[(size_t)(f + 1) * J4_ + j4]);
        float4 v2 = __ldcs(&xb[(size_t)(f + 2) * J4_ + j4]);
        float4 v3 = __ldcs(&xb[(size_t)(f + 3) * J4_ + j4]);
        float4 v4 = __ldcs(&xb[(size_t)(f + 4) * J4_ + j4]);
        float4 v5 = __ldcs(&xb[(size_t)(f + 5) * J4_ + j4]);
        float4 v6 = __ldcs(&xb[(size_t)(f + 6) * J4_ + j4]);
        float4 v7 = __ldcs(&xb[(size_t)(f + 7) * J4_ + j4]);
        ax += (v0.x + v1.x) + (v2.x + v3.x) + ((v4.x + v5.x) + (v6.x + v7.x));
        ay += (v0.y + v1.y) + (v2.y + v3.y) + ((v4.y + v5.y) + (v6.y + v7.y));
        az += (v0.z + v1.z) + (v2.z + v3.z) + ((v4.z + v5.z) + (v6.z + v7.z));
        aw += (v0.w + v1.w) + (v2.w + v3.w) + ((v4.w + v5.w) + (v6.w + v7.w));
    }
    for (; f < f1; f++) {
        float4 v = __ldcs(&xb[(size_t)f * J4_ + j4]);
        ax += v.x; ay += v.y; az += v.z; aw += v.w;
    }
    float* dst = g_pooled + (size_t)b * JC_ + j4 * 4;
    asm volatile("red.global.add.v4.f32 [%0], {%1, %2, %3, %4};"
                 :: "l"(dst), "f"(ax), "f"(ay), "f"(az), "f"(aw)
                 : "memory");
}

// ---------------------------------------------------------------------------
// Kernel 2: FC, W-slice in shared (R9 design) + register headroom.
// grid = (NQ=15, BT_N=16) = 240 blocks, block = 256 (8 warps).
// __launch_bounds__(256, 1): up to 255 regs -> unroll-10 keeps ~20 pooled
// loads in flight (this was the serialized latency chain at regs=32).
// ---------------------------------------------------------------------------
__global__ __launch_bounds__(256, 1) void fc_kernel(
    const float* __restrict__ x,       // [B, F, JC] (len<=1 edge case)
    const int*   __restrict__ lengths, // [B]
    const float* __restrict__ W,       // [JC, NC] row-major
    const float* __restrict__ bias,    // [NC]
    float*       __restrict__ out)     // [B, NC]
{
    __shared__ float4 sW[JC_];         // 25.6 KB: W[:, 4q..4q+3]

    const int q  = blockIdx.x;         // 0..14
    const int b0 = blockIdx.y * BTILE; // batch tile base
    const int t  = threadIdx.x;
    const int w  = t >> 5;             // 0..7
    const int l  = t & 31;

    // ---- load W slice into shared (independent 16B gathers) ----
    const float4* __restrict__ W4 = reinterpret_cast<const float4*>(W); // [JC][15]
#pragma unroll
    for (int j = t; j < JC_; j += 256)
        sW[j] = W4[(size_t)j * NQ + q];
    __syncthreads();

    // ---- two rows per warp (8 FMA chains), deep unroll ----
    const int bA = b0 + w;
    const int bB = b0 + w + 8;
    const int lenA = lengths[bA];
    const int lenB = lengths[bB];
    const float* __restrict__ srcA =
        (lenA <= 1) ? (x + (size_t)bA * F_ * JC_) : (g_pooled + (size_t)bA * JC_);
    const float* __restrict__ srcB =
        (lenB <= 1) ? (x + (size_t)bB * F_ * JC_) : (g_pooled + (size_t)bB * JC_);
    const float invA = (lenA <= 1) ? 1.0f : 1.0f / (float)lenA;
    const float invB = (lenB <= 1) ? 1.0f : 1.0f / (float)lenB;

    float4 a0 = make_float4(0.f, 0.f, 0.f, 0.f);
    float4 a1 = a0;

#pragma unroll 10
    for (int k = 0; k < JC_ / 32; k++) {   // 50 iterations, 10 batched
        const int j = k * 32 + l;
        const float pA = srcA[j];          // coalesced 128B warp load
        const float pB = srcB[j];
        const float4 wv = sW[j];           // conflict-free LDS.128
        a0.x += pA * wv.x; a0.y += pA * wv.y; a0.z += pA * wv.z; a0.w += pA * wv.w;
        a1.x += pB * wv.x; a1.y += pB * wv.y; a1.z += pB * wv.z; a1.w += pB * wv.w;
    }

    // warp-shuffle reduce all 8 components
#pragma unroll
    for (int off = 16; off > 0; off >>= 1) {
        a0.x += __shfl_xor_sync(0xFFFFFFFF, a0.x, off);
        a0.y += __shfl_xor_sync(0xFFFFFFFF, a0.y, off);
        a0.z += __shfl_xor_sync(0xFFFFFFFF, a0.z, off);
        a0.w += __shfl_xor_sync(0xFFFFFFFF, a0.w, off);
        a1.x += __shfl_xor_sync(0xFFFFFFFF, a1.x, off);
        a1.y += __shfl_xor_sync(0xFFFFFFFF, a1.y, off);
        a1.z += __shfl_xor_sync(0xFFFFFFFF, a1.z, off);
        a1.w += __shfl_xor_sync(0xFFFFFFFF, a1.w, off);
    }

    if (l == 0) {
        const int n = 4 * q;
        const float c0 = bias[n + 0], c1 = bias[n + 1];
        const float c2 = bias[n + 2], c3 = bias[n + 3];
        float* oA = out + (size_t)bA * NC_ + n;
        oA[0] = a0.x * invA + c0; oA[1] = a0.y * invA + c1;
        oA[2] = a0.z * invA + c2; oA[3] = a0.w * invA + c3;
        float* oB = out + (size_t)bB * NC_ + n;
        oB[0] = a1.x * invB + c0; oB[1] = a1.y * invB + c1;
        oB[2] = a1.z * invB + c2; oB[3] = a1.w * invB + c3;
    }
}

extern "C" void kernel_launch(void* const* d_in, const int* in_sizes, int n_in,
                              void* d_out, int out_size)
{
    const float* x       = (const float*)d_in[0];
    const int*   lengths = (const int*)  d_in[1];
    const float* W       = (const float*)d_in[2];
    const float* bias    = (const float*)d_in[3];
    float*       out     = (float*)d_out;

    // zero the accumulator (graph-capturable memset node; no allocation)
    void* pooled_ptr = nullptr;
    cudaGetSymbolAddress(&pooled_ptr, g_pooled);
    cudaMemsetAsync(pooled_ptr, 0, sizeof(float) * (size_t)B_ * JC_);

    dim3 grid_pool(B_, NCH);
    pool_part_kernel<<<grid_pool, 400>>>(x, lengths);
    dim3 grid_fc(NQ, BT_N);
    fc_kernel<<<grid_fc, 256>>>(x, lengths, W, bias, out);
}